// round 8
// baseline (speedup 1.0000x reference)
#include <cuda_runtime.h>
#include <cuda_bf16.h>

// WaveletLinear: y[b,o] = sum_i w[o,i] * (1 - s^2) * exp(-0.5 s^2),
//   s = (x[b,i] - t[o,i]) / (A_MIN + softplus(scale_raw[o,i]) + EPS)
// B=512, O=1024, I=512.
//
// Math:  c^2 = 1/(2 ln2),  u = (c*s)^2  (>=0)
//   exp(-0.5 s^2) = 2^(-u)   via ONE ex2.approx.f16x2 per pair (MUFU halved)
//   negation done with xor 0x80008000 on the f16x2 (u >= 0, sign bits clear)
//   w*(1 - s^2)   = fma(w2n, u, w),  w2n = -2ln2*w
// Accumulate with 2 scalar FFMAs (no e repack); round-7 skeleton, occ 4/SM.

#define I_DIM 512
#define RB 8   // batch rows per warp

typedef unsigned long long u64;

__device__ float g_ivc[1024 * 512];
__device__ float g_tin[1024 * 512];
__device__ float g_w2n[1024 * 512];

__device__ __forceinline__ u64 fma2(u64 a, u64 b, u64 c) {
    u64 d; asm("fma.rn.f32x2 %0, %1, %2, %3;" : "=l"(d) : "l"(a), "l"(b), "l"(c)); return d;
}
__device__ __forceinline__ u64 mul2(u64 a, u64 b) {
    u64 d; asm("mul.rn.f32x2 %0, %1, %2;" : "=l"(d) : "l"(a), "l"(b)); return d;
}
__device__ __forceinline__ u64 pack2(float lo, float hi) {
    u64 d; asm("mov.b64 %0, {%1, %2};" : "=l"(d) : "f"(lo), "f"(hi)); return d;
}
__device__ __forceinline__ float lo32(u64 v) { return __uint_as_float((unsigned)v); }
__device__ __forceinline__ float hi32(u64 v) { return __uint_as_float((unsigned)(v >> 32)); }

// packed f32x2 u (>=0) -> e0 = 2^(-u.lo), e1 = 2^(-u.hi) as f32 scalars.
// One f16x2 MUFU slot; negate via sign-bit xor; no repacking.
__device__ __forceinline__ void exp2n_h2(u64 u, float& e0, float& e1) {
    asm("{\n\t"
        ".reg .b32 lo, hi, h;\n\t"
        ".reg .b16 h0, h1;\n\t"
        "mov.b64 {lo, hi}, %2;\n\t"
        "cvt.rn.f16x2.f32 h, hi, lo;\n\t"      // lower=lo, upper=hi
        "xor.b32 h, h, 0x80008000;\n\t"        // -u in both halves
        "ex2.approx.f16x2 h, h;\n\t"           // 2 exps, 1 MUFU slot
        "mov.b32 {h0, h1}, h;\n\t"
        "cvt.f32.f16 %0, h0;\n\t"
        "cvt.f32.f16 %1, h1;\n\t"
        "}" : "=f"(e0), "=f"(e1) : "l"(u));
}

#define C_FOLD   0.84932180028801905f    // sqrt(1/(2 ln2))
#define TWO_LN2  1.38629436111989062f    // 2 ln2
#define NINV2LN2 (-0.72134752044448170f) // -1/(2 ln2)

__global__ void prep_kernel(const float* __restrict__ t,
                            const float* __restrict__ sraw,
                            const float* __restrict__ w,
                            int n)
{
    int idx = blockIdx.x * blockDim.x + threadIdx.x;
    if (idx < n) {
        float z  = sraw[idx];
        float sp = log1pf(__expf(z));
        float sc = 0.001f + sp + 1e-8f;
        float iv = 1.0f / sc;
        g_ivc[idx] = C_FOLD * iv;
        g_tin[idx] = -C_FOLD * t[idx] * iv;
        g_w2n[idx] = -TWO_LN2 * w[idx];
    }
}

__global__ __launch_bounds__(256, 4)
void wavelet_kernel(const float* __restrict__ x,
                    float* __restrict__ out,
                    int O)
{
    const int warp = (blockIdx.x * 256 + threadIdx.x) >> 5;
    const int lane = threadIdx.x & 31;
    const int o  = warp >> 6;       // 8 warps (one block) share o
    const int bt = warp & 63;
    const int b0 = bt * RB;

    const ulonglong2* __restrict__ ivp = (const ulonglong2*)(g_ivc + (size_t)o * I_DIM);
    const ulonglong2* __restrict__ tnp = (const ulonglong2*)(g_tin + (size_t)o * I_DIM);
    const ulonglong2* __restrict__ w2p = (const ulonglong2*)(g_w2n + (size_t)o * I_DIM);
    const ulonglong2* __restrict__ xp  = (const ulonglong2*)(x     + (size_t)b0 * I_DIM);

    const u64 KINV = pack2(NINV2LN2, NINV2LN2);

    // scalar accumulators: lo-half and hi-half chains per batch row
    float acc0[RB], acc1[RB];
#pragma unroll
    for (int b = 0; b < RB; b++) { acc0[b] = 0.0f; acc1[b] = 0.0f; }

#pragma unroll
    for (int step = 0; step < I_DIM / 128; step++) {
        const int i4 = step * 32 + lane;   // 128-bit index: 128 i per step
        const ulonglong2 iv = ivp[i4];
        const ulonglong2 tn = tnp[i4];
        const ulonglong2 w2 = w2p[i4];
        // reconstruct w from w2n once per step (shared by all RB rows)
        const u64 wvx = mul2(w2.x, KINV);
        const u64 wvy = mul2(w2.y, KINV);

#pragma unroll
        for (int b = 0; b < RB; b++) {
            const ulonglong2 xv = xp[i4 + b * (I_DIM / 4)];

            // pair 0
            {
                u64 s  = fma2(xv.x, iv.x, tn.x);
                u64 u  = mul2(s, s);
                float e0, e1; exp2n_h2(u, e0, e1);
                u64 pp = fma2(w2.x, u, wvx);
                acc0[b] = fmaf(lo32(pp), e0, acc0[b]);
                acc1[b] = fmaf(hi32(pp), e1, acc1[b]);
            }
            // pair 1
            {
                u64 s  = fma2(xv.y, iv.y, tn.y);
                u64 u  = mul2(s, s);
                float e0, e1; exp2n_h2(u, e0, e1);
                u64 pp = fma2(w2.y, u, wvy);
                acc0[b] = fmaf(lo32(pp), e0, acc0[b]);
                acc1[b] = fmaf(hi32(pp), e1, acc1[b]);
            }
        }
    }

    // fold the two scalar chains, then warp reduction over i-lanes
#pragma unroll
    for (int b = 0; b < RB; b++) {
        float a = acc0[b] + acc1[b];
#pragma unroll
        for (int off = 16; off > 0; off >>= 1)
            a += __shfl_xor_sync(0xFFFFFFFFu, a, off);
        if (lane == 0)
            out[(size_t)(b0 + b) * O + o] = a;
    }
}

extern "C" void kernel_launch(void* const* d_in, const int* in_sizes, int n_in,
                              void* d_out, int out_size)
{
    const float* x    = (const float*)d_in[0];  // (B, I)
    const float* t    = (const float*)d_in[1];  // (O, I)
    const float* sraw = (const float*)d_in[2];  // (O, I)
    const float* w    = (const float*)d_in[3];  // (O, I)
    float* out = (float*)d_out;                 // (B, O)

    const int OI = in_sizes[1];          // O * I
    const int BI = in_sizes[0];          // B * I
    const int O  = OI / I_DIM;           // 1024
    const int B  = BI / I_DIM;           // 512
    const int nbt = B / RB;              // 64

    prep_kernel<<<(OI + 255) / 256, 256>>>(t, sraw, w, OI);

    const int total_warps = O * nbt;
    wavelet_kernel<<<total_warps / 8, 256>>>(x, out, O);
}